// round 5
// baseline (speedup 1.0000x reference)
#include <cuda_runtime.h>
#include <cuda_bf16.h>
#include <cstdint>

// =============================================================================
// SVDLinearAddition, bf16x3 split-precision on mma.sync (tensor pipe):
//   prep:  xh/xl = split(x); uh/ul = split(U*(S+eps)); vh/vl = split(Vt^T)
//   GEMM1: w = u @ v^T   (split epilogue -> wh/wl bf16)
//   GEMM2: y = x @ w^T + bias (fp32 epilogue)
// 128x256 CTA tile, KC=32, 4-stage cp.async pipeline, one barrier per k-iter.
// =============================================================================

__device__ uint16_t g_xh[8192ull * 4096], g_xl[8192ull * 4096];
__device__ uint16_t g_uh[4096ull * 4096], g_ul[4096ull * 4096];
__device__ uint16_t g_vh[4096ull * 4096], g_vl[4096ull * 4096];
__device__ uint16_t g_wh[4096ull * 4096], g_wl[4096ull * 4096];

// ---------------------------- helpers ---------------------------------------
static __device__ __forceinline__ uint32_t smem_u32(const void* p) {
    uint32_t a;
    asm("{ .reg .u64 t; cvta.to.shared.u64 t, %1; cvt.u32.u64 %0, t; }"
        : "=r"(a) : "l"(p));
    return a;
}
// SW64 swizzle for 64-byte rows: XOR 16B-chunk index (bits 5:4) with row bits (8:7)
static __device__ __forceinline__ uint32_t sw64(uint32_t o) {
    return o ^ ((o >> 3) & 0x30);
}
static __device__ __forceinline__ void ldsm4(uint32_t& r0, uint32_t& r1,
                                             uint32_t& r2, uint32_t& r3, uint32_t a) {
    asm volatile("ldmatrix.sync.aligned.m8n8.x4.shared.b16 {%0,%1,%2,%3}, [%4];"
                 : "=r"(r0), "=r"(r1), "=r"(r2), "=r"(r3) : "r"(a));
}
static __device__ __forceinline__ void mma16816(float& c0, float& c1, float& c2, float& c3,
                                                uint32_t a0, uint32_t a1, uint32_t a2, uint32_t a3,
                                                uint32_t b0, uint32_t b1) {
    asm volatile(
        "mma.sync.aligned.m16n8k16.row.col.f32.bf16.bf16.f32 "
        "{%0,%1,%2,%3}, {%4,%5,%6,%7}, {%8,%9}, {%0,%1,%2,%3};"
        : "+f"(c0), "+f"(c1), "+f"(c2), "+f"(c3)
        : "r"(a0), "r"(a1), "r"(a2), "r"(a3), "r"(b0), "r"(b1));
}
static __device__ __forceinline__ void cpa16(uint32_t s, const void* g) {
    asm volatile("cp.async.cg.shared.global [%0], [%1], 16;" :: "r"(s), "l"(g));
}
static __device__ __forceinline__ void cpa_commit() {
    asm volatile("cp.async.commit_group;");
}
// fp32x4 -> hi/lo bf16x4 split, packed as uint2 each
static __device__ __forceinline__ void split4(float4 v, uint2& hi, uint2& lo) {
    __nv_bfloat162 h01 = __floats2bfloat162_rn(v.x, v.y);
    __nv_bfloat162 h23 = __floats2bfloat162_rn(v.z, v.w);
    float r0 = v.x - __bfloat162float(h01.x);
    float r1 = v.y - __bfloat162float(h01.y);
    float r2 = v.z - __bfloat162float(h23.x);
    float r3 = v.w - __bfloat162float(h23.y);
    __nv_bfloat162 l01 = __floats2bfloat162_rn(r0, r1);
    __nv_bfloat162 l23 = __floats2bfloat162_rn(r2, r3);
    hi.x = *reinterpret_cast<uint32_t*>(&h01);
    hi.y = *reinterpret_cast<uint32_t*>(&h23);
    lo.x = *reinterpret_cast<uint32_t*>(&l01);
    lo.y = *reinterpret_cast<uint32_t*>(&l23);
}

// ------------------------------ prep kernels --------------------------------
__global__ void prep_split(const float* __restrict__ src,
                           uint16_t* __restrict__ hi, uint16_t* __restrict__ lo,
                           size_t n4)
{
    uint2* h2 = reinterpret_cast<uint2*>(hi);
    uint2* l2 = reinterpret_cast<uint2*>(lo);
    for (size_t i = blockIdx.x * blockDim.x + threadIdx.x; i < n4;
         i += (size_t)gridDim.x * blockDim.x) {
        uint2 hu, lu;
        split4(reinterpret_cast<const float4*>(src)[i], hu, lu);
        h2[i] = hu; l2[i] = lu;
    }
}
__global__ void prep_scale_split(const float* __restrict__ U,
                                 const float* __restrict__ S,
                                 const float* __restrict__ eps,
                                 uint16_t* __restrict__ hi, uint16_t* __restrict__ lo,
                                 size_t n4, int rq)
{
    uint2* h2 = reinterpret_cast<uint2*>(hi);
    uint2* l2 = reinterpret_cast<uint2*>(lo);
    for (size_t i = blockIdx.x * blockDim.x + threadIdx.x; i < n4;
         i += (size_t)gridDim.x * blockDim.x) {
        size_t c4 = i % rq;
        float4 v = reinterpret_cast<const float4*>(U)[i];
        float4 sv = reinterpret_cast<const float4*>(S)[c4];
        float4 ev = reinterpret_cast<const float4*>(eps)[c4];
        v.x *= (sv.x + ev.x); v.y *= (sv.y + ev.y);
        v.z *= (sv.z + ev.z); v.w *= (sv.w + ev.w);
        uint2 hu, lu;
        split4(v, hu, lu);
        h2[i] = hu; l2[i] = lu;
    }
}
// Vt [r][dIn] -> vh/vl [dIn][r] (transpose + split)
__global__ void prep_transpose_split(const float* __restrict__ Vt,
                                     uint16_t* __restrict__ hi, uint16_t* __restrict__ lo,
                                     int R, int dIn)
{
    __shared__ float tile[32][33];
    const int tx = threadIdx.x, ty = threadIdx.y;  // 32 x 8
    const int k0 = blockIdx.y * 32, n0 = blockIdx.x * 32;
    #pragma unroll
    for (int j = 0; j < 4; j++)
        tile[ty + j * 8][tx] = Vt[(size_t)(k0 + ty + j * 8) * dIn + n0 + tx];
    __syncthreads();
    #pragma unroll
    for (int j = 0; j < 4; j++) {
        float v = tile[tx][ty + j * 8];
        __nv_bfloat16 h = __float2bfloat16_rn(v);
        __nv_bfloat16 l = __float2bfloat16_rn(v - __bfloat162float(h));
        size_t o = (size_t)(n0 + ty + j * 8) * R + k0 + tx;
        hi[o] = *reinterpret_cast<uint16_t*>(&h);
        lo[o] = *reinterpret_cast<uint16_t*>(&l);
    }
}

// ------------------------------ GEMM core -----------------------------------
// CTA tile 128(m) x 256(n), KC=32 (64B rows, SW64). 8 warps (2m x 4n), 64x64.
// stage: AH 8K | AL 8K | BH 16K | BL 16K = 48KB; 4 stages = 192KB.
#define KC 32
#define T_AH 0
#define T_AL 8192
#define T_BH 16384
#define T_BL 32768
#define STAGE 49152
#define NSTAGE 4
#define SMEM_BYTES (NSTAGE * STAGE)

template<int EPI>   // 0: split-bf16 output (GEMM1), 1: fp32 + bias (GEMM2)
__global__ __launch_bounds__(256, 1)
void gemm_bf16x3(const uint16_t* __restrict__ Agh, const uint16_t* __restrict__ Agl,
                 const uint16_t* __restrict__ Bgh, const uint16_t* __restrict__ Bgl,
                 float* __restrict__ Yout, const float* __restrict__ bias,
                 uint16_t* __restrict__ Wh, uint16_t* __restrict__ Wl,
                 int M, int N, int K)
{
    extern __shared__ char smem[];
    const uint32_t sb = smem_u32(smem);

    const int tid = threadIdx.x;
    const int wid = tid >> 5, lane = tid & 31;
    const int m0 = blockIdx.y * 128;
    const int n0 = blockIdx.x * 256;
    const int mw = (wid & 1) * 64;
    const int nw = (wid >> 1) * 64;

    // ldsm addresses: precompute swizzled (row*64 + col) base; kk adds bit 5 (XOR-safe)
    const uint32_t rowA = mw + (lane & 7) + ((lane >> 3) & 1) * 8;
    const uint32_t colA = ((lane >> 4) & 1) * 16;
    const uint32_t rowB = nw + (lane & 7) + ((lane >> 4) & 1) * 8;
    const uint32_t colB = ((lane >> 3) & 1) * 16;
    uint32_t aAddr[4], bAddr[4];
    #pragma unroll
    for (int mi = 0; mi < 4; mi++) aAddr[mi] = sw64((rowA + mi * 16) * 64 + colA);
    #pragma unroll
    for (int p = 0; p < 4; p++)  bAddr[p]  = sw64((rowB + p * 16) * 64 + colB);

    float acc[4][8][4];
    #pragma unroll
    for (int i = 0; i < 4; i++)
        #pragma unroll
        for (int j = 0; j < 8; j++)
            #pragma unroll
            for (int q = 0; q < 4; q++) acc[i][j][q] = 0.f;

    const int KI = K / KC;

    // per-stage loader: 12 cp.async x 16B per thread
    const int lrow = tid >> 2, lq = tid & 3;
    auto ISSUE = [&](int slot, int kt) {
        const uint32_t base = sb + (uint32_t)slot * STAGE;
        const int k0 = kt * KC;
        #pragma unroll
        for (int i = 0; i < 2; i++) {                  // A halves: 512 chunks each
            int row = lrow + i * 64;
            uint32_t off = sw64((uint32_t)(row * 64 + lq * 16));
            const size_t go = (size_t)(m0 + row) * K + k0 + lq * 8;
            cpa16(base + T_AH + off, Agh + go);
            cpa16(base + T_AL + off, Agl + go);
        }
        #pragma unroll
        for (int i = 0; i < 4; i++) {                  // B halves: 1024 chunks each
            int row = lrow + i * 64;
            uint32_t off = sw64((uint32_t)(row * 64 + lq * 16));
            const size_t go = (size_t)(n0 + row) * K + k0 + lq * 8;
            cpa16(base + T_BH + off, Bgh + go);
            cpa16(base + T_BL + off, Bgl + go);
        }
        cpa_commit();
    };

    ISSUE(0, 0);
    ISSUE(1, 1);
    ISSUE(2, 2);

    for (int kt = 0; kt < KI; kt++) {
        asm volatile("cp.async.wait_group 2;" ::: "memory");
        __syncthreads();
        if (kt + 3 < KI) ISSUE((kt + 3) & (NSTAGE - 1), kt + 3);

        const uint32_t stg = sb + (uint32_t)(kt & (NSTAGE - 1)) * STAGE;

        #pragma unroll
        for (int kk = 0; kk < 2; kk++) {
            const uint32_t kko = (uint32_t)kk << 5;
            uint32_t ah[4][4], al[4][4], bh[4][4], bl[4][4];
            #pragma unroll
            for (int mi = 0; mi < 4; mi++) {
                uint32_t a = stg + (aAddr[mi] ^ kko);
                ldsm4(ah[mi][0], ah[mi][1], ah[mi][2], ah[mi][3], a + T_AH);
                ldsm4(al[mi][0], al[mi][1], al[mi][2], al[mi][3], a + T_AL);
            }
            #pragma unroll
            for (int p = 0; p < 4; p++) {
                uint32_t a = stg + (bAddr[p] ^ kko);
                ldsm4(bh[p][0], bh[p][1], bh[p][2], bh[p][3], a + T_BH);
                ldsm4(bl[p][0], bl[p][1], bl[p][2], bl[p][3], a + T_BL);
            }
            #pragma unroll
            for (int mi = 0; mi < 4; mi++) {
                #pragma unroll
                for (int ni = 0; ni < 8; ni++) {
                    uint32_t vb0 = bh[ni >> 1][(ni & 1) * 2];
                    uint32_t vb1 = bh[ni >> 1][(ni & 1) * 2 + 1];
                    uint32_t wb0 = bl[ni >> 1][(ni & 1) * 2];
                    uint32_t wb1 = bl[ni >> 1][(ni & 1) * 2 + 1];
                    float* c = acc[mi][ni];
                    mma16816(c[0], c[1], c[2], c[3],
                             ah[mi][0], ah[mi][1], ah[mi][2], ah[mi][3], vb0, vb1);
                    mma16816(c[0], c[1], c[2], c[3],
                             ah[mi][0], ah[mi][1], ah[mi][2], ah[mi][3], wb0, wb1);
                    mma16816(c[0], c[1], c[2], c[3],
                             al[mi][0], al[mi][1], al[mi][2], al[mi][3], vb0, vb1);
                }
            }
        }
    }

    // ------------------------------ epilogue ---------------------------------
    const int erow = lane >> 2;
    const int ecol = (lane & 3) * 2;
    if (EPI == 1) {
        #pragma unroll
        for (int ni = 0; ni < 8; ni++) {
            int n = n0 + nw + ni * 8 + ecol;
            float2 bv = *reinterpret_cast<const float2*>(bias + n);
            #pragma unroll
            for (int mi = 0; mi < 4; mi++) {
                int m = m0 + mw + mi * 16 + erow;
                float* c = acc[mi][ni];
                *reinterpret_cast<float2*>(Yout + (size_t)m * N + n) =
                    make_float2(c[0] + bv.x, c[1] + bv.y);
                *reinterpret_cast<float2*>(Yout + (size_t)(m + 8) * N + n) =
                    make_float2(c[2] + bv.x, c[3] + bv.y);
            }
        }
    } else {
        #pragma unroll
        for (int ni = 0; ni < 8; ni++) {
            int n = n0 + nw + ni * 8 + ecol;
            #pragma unroll
            for (int mi = 0; mi < 4; mi++) {
                int m = m0 + mw + mi * 16 + erow;
                float* c = acc[mi][ni];
                #pragma unroll
                for (int half = 0; half < 2; half++) {
                    float v0 = c[half * 2], v1 = c[half * 2 + 1];
                    __nv_bfloat162 h = __floats2bfloat162_rn(v0, v1);
                    __nv_bfloat162 l = __floats2bfloat162_rn(
                        v0 - __bfloat162float(h.x), v1 - __bfloat162float(h.y));
                    size_t o = (size_t)(m + half * 8) * N + n;
                    *reinterpret_cast<uint32_t*>(Wh + o) = *reinterpret_cast<uint32_t*>(&h);
                    *reinterpret_cast<uint32_t*>(Wl + o) = *reinterpret_cast<uint32_t*>(&l);
                }
            }
        }
    }
}

// =============================================================================
// Entry. Inputs: x, U, S, Vt, epsilon, bias
// =============================================================================
extern "C" void kernel_launch(void* const* d_in, const int* in_sizes, int n_in,
                              void* d_out, int out_size)
{
    const float* x    = (const float*)d_in[0];
    const float* U    = (const float*)d_in[1];
    const float* S    = (const float*)d_in[2];
    const float* Vt   = (const float*)d_in[3];
    const float* eps  = (const float*)d_in[4];
    const float* bias = (const float*)d_in[5];
    float* y = (float*)d_out;

    const int r    = in_sizes[2];          // 4096
    const int dIn  = in_sizes[3] / r;      // 4096
    const int dOut = in_sizes[1] / r;      // 4096
    const int M    = in_sizes[0] / dIn;    // 8192

    cudaFuncSetAttribute(gemm_bf16x3<0>, cudaFuncAttributeMaxDynamicSharedMemorySize, SMEM_BYTES);
    cudaFuncSetAttribute(gemm_bf16x3<1>, cudaFuncAttributeMaxDynamicSharedMemorySize, SMEM_BYTES);

    uint16_t *xh, *xl, *uh, *ul, *vh, *vl, *wh, *wl;
    cudaGetSymbolAddress((void**)&xh, g_xh);
    cudaGetSymbolAddress((void**)&xl, g_xl);
    cudaGetSymbolAddress((void**)&uh, g_uh);
    cudaGetSymbolAddress((void**)&ul, g_ul);
    cudaGetSymbolAddress((void**)&vh, g_vh);
    cudaGetSymbolAddress((void**)&vl, g_vl);
    cudaGetSymbolAddress((void**)&wh, g_wh);
    cudaGetSymbolAddress((void**)&wl, g_wl);

    prep_split<<<4096, 256>>>(x, xh, xl, (size_t)M * dIn / 4);
    prep_scale_split<<<4096, 256>>>(U, S, eps, uh, ul, (size_t)dOut * r / 4, r / 4);
    {
        dim3 grid(dIn / 32, r / 32), blk(32, 8);
        prep_transpose_split<<<grid, blk>>>(Vt, vh, vl, r, dIn);
    }
    {
        dim3 grid(dIn / 256, dOut / 128);
        gemm_bf16x3<0><<<grid, 256, SMEM_BYTES>>>(uh, ul, vh, vl,
                                                  nullptr, nullptr, wh, wl,
                                                  dOut, dIn, r);
    }
    {
        dim3 grid(dOut / 256, M / 128);
        gemm_bf16x3<1><<<grid, 256, SMEM_BYTES>>>(xh, xl, wh, wl,
                                                  y, bias, nullptr, nullptr,
                                                  M, dOut, dIn);
    }
}

// round 6
// speedup vs baseline: 1.5204x; 1.5204x over previous
#include <cuda_runtime.h>
#include <cuda_fp16.h>
#include <cstdint>

// =============================================================================
// SVDLinearAddition, fp16 2-product split-precision on mma.sync:
//   ŷ = Σ ah·(bh+bl): A side fp16-hi only (11-bit), B side fp16 hi+lo (22-bit)
//   prep:  xh = fp16(x); uh = fp16(U*(S+eps)); (vh,vl) = split16(Vt^T)
//   GEMM1: w = uh @ (vh+vl)^T   -> split fp16 epilogue (wh, wl)
//   GEMM2: y = xh @ (wh+wl)^T + bias (fp32 epilogue)
// 128x256 CTA tile, KC=64, 2-stage cp.async pipeline (round-4 structure).
// =============================================================================

__device__ uint16_t g_xh[8192ull * 4096];
__device__ uint16_t g_uh[4096ull * 4096];
__device__ uint16_t g_vh[4096ull * 4096], g_vl[4096ull * 4096];
__device__ uint16_t g_wh[4096ull * 4096], g_wl[4096ull * 4096];

// ---------------------------- helpers ---------------------------------------
static __device__ __forceinline__ uint32_t smem_u32(const void* p) {
    uint32_t a;
    asm("{ .reg .u64 t; cvta.to.shared.u64 t, %1; cvt.u32.u64 %0, t; }"
        : "=r"(a) : "l"(p));
    return a;
}
static __device__ __forceinline__ uint32_t sw128(uint32_t o) {
    return o ^ ((o >> 3) & 0x70);
}
static __device__ __forceinline__ void ldsm4(uint32_t& r0, uint32_t& r1,
                                             uint32_t& r2, uint32_t& r3, uint32_t a) {
    asm volatile("ldmatrix.sync.aligned.m8n8.x4.shared.b16 {%0,%1,%2,%3}, [%4];"
                 : "=r"(r0), "=r"(r1), "=r"(r2), "=r"(r3) : "r"(a));
}
static __device__ __forceinline__ void mma16816(float& c0, float& c1, float& c2, float& c3,
                                                uint32_t a0, uint32_t a1, uint32_t a2, uint32_t a3,
                                                uint32_t b0, uint32_t b1) {
    asm volatile(
        "mma.sync.aligned.m16n8k16.row.col.f32.f16.f16.f32 "
        "{%0,%1,%2,%3}, {%4,%5,%6,%7}, {%8,%9}, {%0,%1,%2,%3};"
        : "+f"(c0), "+f"(c1), "+f"(c2), "+f"(c3)
        : "r"(a0), "r"(a1), "r"(a2), "r"(a3), "r"(b0), "r"(b1));
}
static __device__ __forceinline__ void cpa16(uint32_t s, const void* g) {
    asm volatile("cp.async.cg.shared.global [%0], [%1], 16;" :: "r"(s), "l"(g));
}
static __device__ __forceinline__ void cpa_commit() {
    asm volatile("cp.async.commit_group;");
}
// fp32x4 -> hi/lo fp16x4 split
static __device__ __forceinline__ void split4h(float4 v, uint2& hi, uint2& lo) {
    __half2 h01 = __floats2half2_rn(v.x, v.y);
    __half2 h23 = __floats2half2_rn(v.z, v.w);
    float r0 = v.x - __half2float(h01.x);
    float r1 = v.y - __half2float(h01.y);
    float r2 = v.z - __half2float(h23.x);
    float r3 = v.w - __half2float(h23.y);
    __half2 l01 = __floats2half2_rn(r0, r1);
    __half2 l23 = __floats2half2_rn(r2, r3);
    hi.x = *reinterpret_cast<uint32_t*>(&h01);
    hi.y = *reinterpret_cast<uint32_t*>(&h23);
    lo.x = *reinterpret_cast<uint32_t*>(&l01);
    lo.y = *reinterpret_cast<uint32_t*>(&l23);
}

// ------------------------------ prep kernels --------------------------------
__global__ void prep_half(const float* __restrict__ src,
                          uint16_t* __restrict__ hi, size_t n4)
{
    uint2* h2 = reinterpret_cast<uint2*>(hi);
    for (size_t i = blockIdx.x * blockDim.x + threadIdx.x; i < n4;
         i += (size_t)gridDim.x * blockDim.x) {
        float4 v = reinterpret_cast<const float4*>(src)[i];
        __half2 h01 = __floats2half2_rn(v.x, v.y);
        __half2 h23 = __floats2half2_rn(v.z, v.w);
        uint2 hu;
        hu.x = *reinterpret_cast<uint32_t*>(&h01);
        hu.y = *reinterpret_cast<uint32_t*>(&h23);
        h2[i] = hu;
    }
}
__global__ void prep_scale_half(const float* __restrict__ U,
                                const float* __restrict__ S,
                                const float* __restrict__ eps,
                                uint16_t* __restrict__ hi, size_t n4, int rq)
{
    uint2* h2 = reinterpret_cast<uint2*>(hi);
    for (size_t i = blockIdx.x * blockDim.x + threadIdx.x; i < n4;
         i += (size_t)gridDim.x * blockDim.x) {
        size_t c4 = i % rq;
        float4 v = reinterpret_cast<const float4*>(U)[i];
        float4 sv = reinterpret_cast<const float4*>(S)[c4];
        float4 ev = reinterpret_cast<const float4*>(eps)[c4];
        v.x *= (sv.x + ev.x); v.y *= (sv.y + ev.y);
        v.z *= (sv.z + ev.z); v.w *= (sv.w + ev.w);
        __half2 h01 = __floats2half2_rn(v.x, v.y);
        __half2 h23 = __floats2half2_rn(v.z, v.w);
        uint2 hu;
        hu.x = *reinterpret_cast<uint32_t*>(&h01);
        hu.y = *reinterpret_cast<uint32_t*>(&h23);
        h2[i] = hu;
    }
}
// Vt [r][dIn] -> vh/vl fp16 [dIn][r] (transpose + split)
__global__ void prep_transpose_split(const float* __restrict__ Vt,
                                     uint16_t* __restrict__ hi, uint16_t* __restrict__ lo,
                                     int R, int dIn)
{
    __shared__ float tile[32][33];
    const int tx = threadIdx.x, ty = threadIdx.y;  // 32 x 8
    const int k0 = blockIdx.y * 32, n0 = blockIdx.x * 32;
    #pragma unroll
    for (int j = 0; j < 4; j++)
        tile[ty + j * 8][tx] = Vt[(size_t)(k0 + ty + j * 8) * dIn + n0 + tx];
    __syncthreads();
    #pragma unroll
    for (int j = 0; j < 4; j++) {
        float v = tile[tx][ty + j * 8];
        __half h = __float2half_rn(v);
        __half l = __float2half_rn(v - __half2float(h));
        size_t o = (size_t)(n0 + ty + j * 8) * R + k0 + tx;
        hi[o] = *reinterpret_cast<uint16_t*>(&h);
        lo[o] = *reinterpret_cast<uint16_t*>(&l);
    }
}

// ------------------------------ GEMM core -----------------------------------
// CTA tile 128(m) x 256(n), KC=64 (128B rows, SW128). 8 warps (2m x 4n), 64x64.
// stage: AH 16K | BH 32K | BL 32K = 80KB; 2 stages = 160KB.
#define KC 64
#define T_AH 0
#define T_BH 16384
#define T_BL 49152
#define STAGE 81920
#define SMEM_BYTES (2 * STAGE)

template<int EPI>   // 0: split-fp16 output (GEMM1), 1: fp32 + bias (GEMM2)
__global__ __launch_bounds__(256, 1)
void gemm_f16x2(const uint16_t* __restrict__ Agh,
                const uint16_t* __restrict__ Bgh, const uint16_t* __restrict__ Bgl,
                float* __restrict__ Yout, const float* __restrict__ bias,
                uint16_t* __restrict__ Wh, uint16_t* __restrict__ Wl,
                int M, int N, int K)
{
    extern __shared__ char smem[];
    const uint32_t sb = smem_u32(smem);

    const int tid = threadIdx.x;
    const int wid = tid >> 5, lane = tid & 31;
    const int m0 = blockIdx.y * 128;
    const int n0 = blockIdx.x * 256;
    const int mw = (wid & 1) * 64;
    const int nw = (wid >> 1) * 64;

    const uint32_t rowA = mw + (lane & 7) + ((lane >> 3) & 1) * 8;
    const uint32_t colA = ((lane >> 4) & 1) * 16;
    const uint32_t rowB = nw + (lane & 7) + ((lane >> 4) & 1) * 8;
    const uint32_t colB = ((lane >> 3) & 1) * 16;

    float acc[4][8][4];
    #pragma unroll
    for (int i = 0; i < 4; i++)
        #pragma unroll
        for (int j = 0; j < 8; j++)
            #pragma unroll
            for (int q = 0; q < 4; q++) acc[i][j][q] = 0.f;

    const int KI = K / KC;

    // stage loader: 20 cp.async x 16B per thread
    auto ISSUE = [&](int stg, int kt) {
        const uint32_t base = sb + (uint32_t)stg * STAGE;
        const int k0 = kt * KC;
        #pragma unroll
        for (int i = 0; i < 4; i++) {                  // A hi: 1024 chunks
            int c = tid + i * 256, row = c >> 3, q = c & 7;
            uint32_t off = sw128((uint32_t)(row * 128 + q * 16));
            cpa16(base + T_AH + off, Agh + (size_t)(m0 + row) * K + k0 + q * 8);
        }
        #pragma unroll
        for (int i = 0; i < 8; i++) {                  // B hi+lo: 2048 chunks each
            int c = tid + i * 256, row = c >> 3, q = c & 7;
            uint32_t off = sw128((uint32_t)(row * 128 + q * 16));
            const size_t go = (size_t)(n0 + row) * K + k0 + q * 8;
            cpa16(base + T_BH + off, Bgh + go);
            cpa16(base + T_BL + off, Bgl + go);
        }
        cpa_commit();
    };

    ISSUE(0, 0);

    for (int kt = 0; kt < KI; kt++) {
        const bool hasNext = (kt + 1 < KI);
        if (hasNext) ISSUE((kt + 1) & 1, kt + 1);
        if (hasNext) asm volatile("cp.async.wait_group 1;" ::: "memory");
        else         asm volatile("cp.async.wait_group 0;" ::: "memory");
        __syncthreads();

        const uint32_t Ah = sb + (uint32_t)(kt & 1) * STAGE + T_AH;
        const uint32_t Bh = sb + (uint32_t)(kt & 1) * STAGE + T_BH;
        const uint32_t Bl = Bh + (T_BL - T_BH);

        #pragma unroll
        for (int kk = 0; kk < 4; kk++) {
            uint32_t ah[4][4], bh[4][4], bl[4][4];
            #pragma unroll
            for (int mi = 0; mi < 4; mi++) {
                uint32_t off = sw128((rowA + mi * 16) * 128 + kk * 32 + colA);
                ldsm4(ah[mi][0], ah[mi][1], ah[mi][2], ah[mi][3], Ah + off);
            }
            #pragma unroll
            for (int p = 0; p < 4; p++) {
                uint32_t off = sw128((rowB + p * 16) * 128 + kk * 32 + colB);
                ldsm4(bh[p][0], bh[p][1], bh[p][2], bh[p][3], Bh + off);
                ldsm4(bl[p][0], bl[p][1], bl[p][2], bl[p][3], Bl + off);
            }
            #pragma unroll
            for (int mi = 0; mi < 4; mi++) {
                #pragma unroll
                for (int ni = 0; ni < 8; ni++) {
                    uint32_t vb0 = bh[ni >> 1][(ni & 1) * 2];
                    uint32_t vb1 = bh[ni >> 1][(ni & 1) * 2 + 1];
                    uint32_t wb0 = bl[ni >> 1][(ni & 1) * 2];
                    uint32_t wb1 = bl[ni >> 1][(ni & 1) * 2 + 1];
                    float* c = acc[mi][ni];
                    mma16816(c[0], c[1], c[2], c[3],
                             ah[mi][0], ah[mi][1], ah[mi][2], ah[mi][3], vb0, vb1);
                    mma16816(c[0], c[1], c[2], c[3],
                             ah[mi][0], ah[mi][1], ah[mi][2], ah[mi][3], wb0, wb1);
                }
            }
        }
        __syncthreads();
    }

    // ------------------------------ epilogue ---------------------------------
    const int erow = lane >> 2;
    const int ecol = (lane & 3) * 2;
    if (EPI == 1) {
        #pragma unroll
        for (int ni = 0; ni < 8; ni++) {
            int n = n0 + nw + ni * 8 + ecol;
            float2 bv = *reinterpret_cast<const float2*>(bias + n);
            #pragma unroll
            for (int mi = 0; mi < 4; mi++) {
                int m = m0 + mw + mi * 16 + erow;
                float* c = acc[mi][ni];
                *reinterpret_cast<float2*>(Yout + (size_t)m * N + n) =
                    make_float2(c[0] + bv.x, c[1] + bv.y);
                *reinterpret_cast<float2*>(Yout + (size_t)(m + 8) * N + n) =
                    make_float2(c[2] + bv.x, c[3] + bv.y);
            }
        }
    } else {
        #pragma unroll
        for (int ni = 0; ni < 8; ni++) {
            int n = n0 + nw + ni * 8 + ecol;
            #pragma unroll
            for (int mi = 0; mi < 4; mi++) {
                int m = m0 + mw + mi * 16 + erow;
                float* c = acc[mi][ni];
                #pragma unroll
                for (int half = 0; half < 2; half++) {
                    float v0 = c[half * 2], v1 = c[half * 2 + 1];
                    __half2 h = __floats2half2_rn(v0, v1);
                    __half2 l = __floats2half2_rn(
                        v0 - __half2float(h.x), v1 - __half2float(h.y));
                    size_t o = (size_t)(m + half * 8) * N + n;
                    *reinterpret_cast<uint32_t*>(Wh + o) = *reinterpret_cast<uint32_t*>(&h);
                    *reinterpret_cast<uint32_t*>(Wl + o) = *reinterpret_cast<uint32_t*>(&l);
                }
            }
        }
    }
}

// =============================================================================
// Entry. Inputs: x, U, S, Vt, epsilon, bias
// =============================================================================
extern "C" void kernel_launch(void* const* d_in, const int* in_sizes, int n_in,
                              void* d_out, int out_size)
{
    const float* x    = (const float*)d_in[0];
    const float* U    = (const float*)d_in[1];
    const float* S    = (const float*)d_in[2];
    const float* Vt   = (const float*)d_in[3];
    const float* eps  = (const float*)d_in[4];
    const float* bias = (const float*)d_in[5];
    float* y = (float*)d_out;

    const int r    = in_sizes[2];          // 4096
    const int dIn  = in_sizes[3] / r;      // 4096
    const int dOut = in_sizes[1] / r;      // 4096
    const int M    = in_sizes[0] / dIn;    // 8192

    cudaFuncSetAttribute(gemm_f16x2<0>, cudaFuncAttributeMaxDynamicSharedMemorySize, SMEM_BYTES);
    cudaFuncSetAttribute(gemm_f16x2<1>, cudaFuncAttributeMaxDynamicSharedMemorySize, SMEM_BYTES);

    uint16_t *xh, *uh, *vh, *vl, *wh, *wl;
    cudaGetSymbolAddress((void**)&xh, g_xh);
    cudaGetSymbolAddress((void**)&uh, g_uh);
    cudaGetSymbolAddress((void**)&vh, g_vh);
    cudaGetSymbolAddress((void**)&vl, g_vl);
    cudaGetSymbolAddress((void**)&wh, g_wh);
    cudaGetSymbolAddress((void**)&wl, g_wl);

    prep_half<<<4096, 256>>>(x, xh, (size_t)M * dIn / 4);
    prep_scale_half<<<4096, 256>>>(U, S, eps, uh, (size_t)dOut * r / 4, r / 4);
    {
        dim3 grid(dIn / 32, r / 32), blk(32, 8);
        prep_transpose_split<<<grid, blk>>>(Vt, vh, vl, r, dIn);
    }
    // GEMM1: w[dOut, dIn] = uh @ (vh+vl)^T (split fp16 output)
    {
        dim3 grid(dIn / 256, dOut / 128);
        gemm_f16x2<0><<<grid, 256, SMEM_BYTES>>>(uh, vh, vl,
                                                 nullptr, nullptr, wh, wl,
                                                 dOut, dIn, r);
    }
    // GEMM2: y[M, dOut] = xh @ (wh+wl)^T + bias
    {
        dim3 grid(dOut / 256, M / 128);
        gemm_f16x2<1><<<grid, 256, SMEM_BYTES>>>(xh, wh, wl,
                                                 y, bias, nullptr, nullptr,
                                                 M, dOut, dIn);
    }
}

// round 7
// speedup vs baseline: 2.8061x; 1.8457x over previous
#include <cuda_runtime.h>
#include <cuda_fp16.h>
#include <cstdint>

// =============================================================================
// SVDLinearAddition, single-product fp16 on mma.sync (tensor pipe):
//   prep:  xh = fp16(x); uh = fp16(U*(S+eps)); vh = fp16(Vt^T)
//   GEMM1: w = uh @ vh^T          -> fp16 epilogue (wh)
//   GEMM2: y = xh @ wh^T + bias   -> fp32 epilogue
// 128x256 CTA tile, KC=64, 3-stage cp.async pipeline, ONE barrier per k-iter.
// Error budget (calibrated from rounds 3/6): ~4.2e-4 rel, threshold 1e-3.
// =============================================================================

__device__ uint16_t g_xh[8192ull * 4096];
__device__ uint16_t g_uh[4096ull * 4096];
__device__ uint16_t g_vh[4096ull * 4096];
__device__ uint16_t g_wh[4096ull * 4096];

// ---------------------------- helpers ---------------------------------------
static __device__ __forceinline__ uint32_t smem_u32(const void* p) {
    uint32_t a;
    asm("{ .reg .u64 t; cvta.to.shared.u64 t, %1; cvt.u32.u64 %0, t; }"
        : "=r"(a) : "l"(p));
    return a;
}
static __device__ __forceinline__ uint32_t sw128(uint32_t o) {
    return o ^ ((o >> 3) & 0x70);
}
static __device__ __forceinline__ void ldsm4(uint32_t& r0, uint32_t& r1,
                                             uint32_t& r2, uint32_t& r3, uint32_t a) {
    asm volatile("ldmatrix.sync.aligned.m8n8.x4.shared.b16 {%0,%1,%2,%3}, [%4];"
                 : "=r"(r0), "=r"(r1), "=r"(r2), "=r"(r3) : "r"(a));
}
static __device__ __forceinline__ void mma16816(float& c0, float& c1, float& c2, float& c3,
                                                uint32_t a0, uint32_t a1, uint32_t a2, uint32_t a3,
                                                uint32_t b0, uint32_t b1) {
    asm volatile(
        "mma.sync.aligned.m16n8k16.row.col.f32.f16.f16.f32 "
        "{%0,%1,%2,%3}, {%4,%5,%6,%7}, {%8,%9}, {%0,%1,%2,%3};"
        : "+f"(c0), "+f"(c1), "+f"(c2), "+f"(c3)
        : "r"(a0), "r"(a1), "r"(a2), "r"(a3), "r"(b0), "r"(b1));
}
static __device__ __forceinline__ void cpa16(uint32_t s, const void* g) {
    asm volatile("cp.async.cg.shared.global [%0], [%1], 16;" :: "r"(s), "l"(g));
}
static __device__ __forceinline__ void cpa_commit() {
    asm volatile("cp.async.commit_group;");
}

// ------------------------------ prep kernels --------------------------------
__global__ void prep_half(const float* __restrict__ src,
                          uint16_t* __restrict__ hi, size_t n4)
{
    uint2* h2 = reinterpret_cast<uint2*>(hi);
    for (size_t i = blockIdx.x * blockDim.x + threadIdx.x; i < n4;
         i += (size_t)gridDim.x * blockDim.x) {
        float4 v = reinterpret_cast<const float4*>(src)[i];
        __half2 h01 = __floats2half2_rn(v.x, v.y);
        __half2 h23 = __floats2half2_rn(v.z, v.w);
        uint2 hu;
        hu.x = *reinterpret_cast<uint32_t*>(&h01);
        hu.y = *reinterpret_cast<uint32_t*>(&h23);
        h2[i] = hu;
    }
}
__global__ void prep_scale_half(const float* __restrict__ U,
                                const float* __restrict__ S,
                                const float* __restrict__ eps,
                                uint16_t* __restrict__ hi, size_t n4, int rq)
{
    uint2* h2 = reinterpret_cast<uint2*>(hi);
    for (size_t i = blockIdx.x * blockDim.x + threadIdx.x; i < n4;
         i += (size_t)gridDim.x * blockDim.x) {
        size_t c4 = i % rq;
        float4 v = reinterpret_cast<const float4*>(U)[i];
        float4 sv = reinterpret_cast<const float4*>(S)[c4];
        float4 ev = reinterpret_cast<const float4*>(eps)[c4];
        v.x *= (sv.x + ev.x); v.y *= (sv.y + ev.y);
        v.z *= (sv.z + ev.z); v.w *= (sv.w + ev.w);
        __half2 h01 = __floats2half2_rn(v.x, v.y);
        __half2 h23 = __floats2half2_rn(v.z, v.w);
        uint2 hu;
        hu.x = *reinterpret_cast<uint32_t*>(&h01);
        hu.y = *reinterpret_cast<uint32_t*>(&h23);
        h2[i] = hu;
    }
}
// Vt [r][dIn] -> vh fp16 [dIn][r] (transpose)
__global__ void prep_transpose_half(const float* __restrict__ Vt,
                                    uint16_t* __restrict__ hi, int R, int dIn)
{
    __shared__ float tile[32][33];
    const int tx = threadIdx.x, ty = threadIdx.y;  // 32 x 8
    const int k0 = blockIdx.y * 32, n0 = blockIdx.x * 32;
    #pragma unroll
    for (int j = 0; j < 4; j++)
        tile[ty + j * 8][tx] = Vt[(size_t)(k0 + ty + j * 8) * dIn + n0 + tx];
    __syncthreads();
    #pragma unroll
    for (int j = 0; j < 4; j++) {
        float v = tile[tx][ty + j * 8];
        __half h = __float2half_rn(v);
        hi[(size_t)(n0 + ty + j * 8) * R + k0 + tx] = *reinterpret_cast<uint16_t*>(&h);
    }
}

// ------------------------------ GEMM core -----------------------------------
// CTA tile 128(m) x 256(n), KC=64 (128B rows, SW128). 8 warps (2m x 4n), 64x64.
// stage: AH 16K | BH 32K = 48KB; 3 stages = 144KB. One __syncthreads per iter.
#define KC 64
#define T_AH 0
#define T_BH 16384
#define STAGE 49152
#define NSTAGE 3
#define SMEM_BYTES (NSTAGE * STAGE)

template<int EPI>   // 0: fp16 output (GEMM1), 1: fp32 + bias (GEMM2)
__global__ __launch_bounds__(256, 1)
void gemm_f16(const uint16_t* __restrict__ Agh,
              const uint16_t* __restrict__ Bgh,
              float* __restrict__ Yout, const float* __restrict__ bias,
              uint16_t* __restrict__ Wh,
              int M, int N, int K)
{
    extern __shared__ char smem[];
    const uint32_t sb = smem_u32(smem);

    const int tid = threadIdx.x;
    const int wid = tid >> 5, lane = tid & 31;
    const int m0 = blockIdx.y * 128;
    const int n0 = blockIdx.x * 256;
    const int mw = (wid & 1) * 64;
    const int nw = (wid >> 1) * 64;

    const uint32_t rowA = mw + (lane & 7) + ((lane >> 3) & 1) * 8;
    const uint32_t colA = ((lane >> 4) & 1) * 16;
    const uint32_t rowB = nw + (lane & 7) + ((lane >> 4) & 1) * 8;
    const uint32_t colB = ((lane >> 3) & 1) * 16;

    float acc[4][8][4];
    #pragma unroll
    for (int i = 0; i < 4; i++)
        #pragma unroll
        for (int j = 0; j < 8; j++)
            #pragma unroll
            for (int q = 0; q < 4; q++) acc[i][j][q] = 0.f;

    const int KI = K / KC;

    // stage loader: 12 cp.async x 16B per thread
    auto ISSUE = [&](int slot, int kt) {
        const uint32_t base = sb + (uint32_t)slot * STAGE;
        const int k0 = kt * KC;
        #pragma unroll
        for (int i = 0; i < 4; i++) {                  // A: 1024 chunks
            int c = tid + i * 256, row = c >> 3, q = c & 7;
            uint32_t off = sw128((uint32_t)(row * 128 + q * 16));
            cpa16(base + T_AH + off, Agh + (size_t)(m0 + row) * K + k0 + q * 8);
        }
        #pragma unroll
        for (int i = 0; i < 8; i++) {                  // B: 2048 chunks
            int c = tid + i * 256, row = c >> 3, q = c & 7;
            uint32_t off = sw128((uint32_t)(row * 128 + q * 16));
            cpa16(base + T_BH + off, Bgh + (size_t)(n0 + row) * K + k0 + q * 8);
        }
        cpa_commit();
    };

    // prologue: fill NSTAGE-1 slots
    ISSUE(0, 0);
    ISSUE(1, 1);

    for (int kt = 0; kt < KI; kt++) {
        asm volatile("cp.async.wait_group %0;" :: "n"(NSTAGE - 2) : "memory");
        __syncthreads();
        // slot (kt-1)%NSTAGE was drained by all warps (fenced by the sync above)
        if (kt + NSTAGE - 1 < KI)
            ISSUE((kt + NSTAGE - 1) % NSTAGE, kt + NSTAGE - 1);

        const uint32_t Ah = sb + (uint32_t)(kt % NSTAGE) * STAGE + T_AH;
        const uint32_t Bh = Ah + (T_BH - T_AH);

        #pragma unroll
        for (int kk = 0; kk < 4; kk++) {
            uint32_t ah[4][4], bh[4][4];
            #pragma unroll
            for (int mi = 0; mi < 4; mi++) {
                uint32_t off = sw128((rowA + mi * 16) * 128 + kk * 32 + colA);
                ldsm4(ah[mi][0], ah[mi][1], ah[mi][2], ah[mi][3], Ah + off);
            }
            #pragma unroll
            for (int p = 0; p < 4; p++) {
                uint32_t off = sw128((rowB + p * 16) * 128 + kk * 32 + colB);
                ldsm4(bh[p][0], bh[p][1], bh[p][2], bh[p][3], Bh + off);
            }
            #pragma unroll
            for (int mi = 0; mi < 4; mi++) {
                #pragma unroll
                for (int ni = 0; ni < 8; ni++) {
                    float* c = acc[mi][ni];
                    mma16816(c[0], c[1], c[2], c[3],
                             ah[mi][0], ah[mi][1], ah[mi][2], ah[mi][3],
                             bh[ni >> 1][(ni & 1) * 2], bh[ni >> 1][(ni & 1) * 2 + 1]);
                }
            }
        }
    }

    // ------------------------------ epilogue ---------------------------------
    const int erow = lane >> 2;
    const int ecol = (lane & 3) * 2;
    if (EPI == 1) {
        #pragma unroll
        for (int ni = 0; ni < 8; ni++) {
            int n = n0 + nw + ni * 8 + ecol;
            float2 bv = *reinterpret_cast<const float2*>(bias + n);
            #pragma unroll
            for (int mi = 0; mi < 4; mi++) {
                int m = m0 + mw + mi * 16 + erow;
                float* c = acc[mi][ni];
                *reinterpret_cast<float2*>(Yout + (size_t)m * N + n) =
                    make_float2(c[0] + bv.x, c[1] + bv.y);
                *reinterpret_cast<float2*>(Yout + (size_t)(m + 8) * N + n) =
                    make_float2(c[2] + bv.x, c[3] + bv.y);
            }
        }
    } else {
        #pragma unroll
        for (int ni = 0; ni < 8; ni++) {
            int n = n0 + nw + ni * 8 + ecol;
            #pragma unroll
            for (int mi = 0; mi < 4; mi++) {
                int m = m0 + mw + mi * 16 + erow;
                float* c = acc[mi][ni];
                #pragma unroll
                for (int half = 0; half < 2; half++) {
                    __half2 h = __floats2half2_rn(c[half * 2], c[half * 2 + 1]);
                    *reinterpret_cast<uint32_t*>(Wh + (size_t)(m + half * 8) * N + n) =
                        *reinterpret_cast<uint32_t*>(&h);
                }
            }
        }
    }
}

// =============================================================================
// Entry. Inputs: x, U, S, Vt, epsilon, bias
// =============================================================================
extern "C" void kernel_launch(void* const* d_in, const int* in_sizes, int n_in,
                              void* d_out, int out_size)
{
    const float* x    = (const float*)d_in[0];
    const float* U    = (const float*)d_in[1];
    const float* S    = (const float*)d_in[2];
    const float* Vt   = (const float*)d_in[3];
    const float* eps  = (const float*)d_in[4];
    const float* bias = (const float*)d_in[5];
    float* y = (float*)d_out;

    const int r    = in_sizes[2];          // 4096
    const int dIn  = in_sizes[3] / r;      // 4096
    const int dOut = in_sizes[1] / r;      // 4096
    const int M    = in_sizes[0] / dIn;    // 8192

    cudaFuncSetAttribute(gemm_f16<0>, cudaFuncAttributeMaxDynamicSharedMemorySize, SMEM_BYTES);
    cudaFuncSetAttribute(gemm_f16<1>, cudaFuncAttributeMaxDynamicSharedMemorySize, SMEM_BYTES);

    uint16_t *xh, *uh, *vh, *wh;
    cudaGetSymbolAddress((void**)&xh, g_xh);
    cudaGetSymbolAddress((void**)&uh, g_uh);
    cudaGetSymbolAddress((void**)&vh, g_vh);
    cudaGetSymbolAddress((void**)&wh, g_wh);

    prep_half<<<4096, 256>>>(x, xh, (size_t)M * dIn / 4);
    prep_scale_half<<<4096, 256>>>(U, S, eps, uh, (size_t)dOut * r / 4, r / 4);
    {
        dim3 grid(dIn / 32, r / 32), blk(32, 8);
        prep_transpose_half<<<grid, blk>>>(Vt, vh, r, dIn);
    }
    // GEMM1: w[dOut, dIn] = uh @ vh^T (fp16 output)
    {
        dim3 grid(dIn / 256, dOut / 128);
        gemm_f16<0><<<grid, 256, SMEM_BYTES>>>(uh, vh, nullptr, nullptr, wh,
                                               dOut, dIn, r);
    }
    // GEMM2: y[M, dOut] = xh @ wh^T + bias
    {
        dim3 grid(dOut / 256, M / 128);
        gemm_f16<1><<<grid, 256, SMEM_BYTES>>>(xh, wh, y, bias, nullptr,
                                               M, dOut, dIn);
    }
}

// round 8
// speedup vs baseline: 2.9103x; 1.0371x over previous
#include <cuda_runtime.h>
#include <cuda_fp16.h>
#include <cstdint>

// =============================================================================
// SVDLinearAddition, single-product fp16 on mma.sync (tensor pipe):
//   prep:  xh = fp16(x); uh = fp16(U*(S+eps)); vh = fp16(Vt^T)
//   GEMM1: w = uh @ vh^T          -> fp16 epilogue (wh)
//   GEMM2: y = xh @ wh^T + bias   -> fp32 epilogue
// 128x128 CTA tile, warp tile 64x32, KC=64, 3-stage cp.async, one barrier/iter,
// 2 CTAs per SM (4 warps/SMSP) to fill the tensor pipe.
// =============================================================================

__device__ uint16_t g_xh[8192ull * 4096];
__device__ uint16_t g_uh[4096ull * 4096];
__device__ uint16_t g_vh[4096ull * 4096];
__device__ uint16_t g_wh[4096ull * 4096];

// ---------------------------- helpers ---------------------------------------
static __device__ __forceinline__ uint32_t smem_u32(const void* p) {
    uint32_t a;
    asm("{ .reg .u64 t; cvta.to.shared.u64 t, %1; cvt.u32.u64 %0, t; }"
        : "=r"(a) : "l"(p));
    return a;
}
static __device__ __forceinline__ uint32_t sw128(uint32_t o) {
    return o ^ ((o >> 3) & 0x70);
}
static __device__ __forceinline__ void ldsm4(uint32_t& r0, uint32_t& r1,
                                             uint32_t& r2, uint32_t& r3, uint32_t a) {
    asm volatile("ldmatrix.sync.aligned.m8n8.x4.shared.b16 {%0,%1,%2,%3}, [%4];"
                 : "=r"(r0), "=r"(r1), "=r"(r2), "=r"(r3) : "r"(a));
}
static __device__ __forceinline__ void mma16816(float& c0, float& c1, float& c2, float& c3,
                                                uint32_t a0, uint32_t a1, uint32_t a2, uint32_t a3,
                                                uint32_t b0, uint32_t b1) {
    asm volatile(
        "mma.sync.aligned.m16n8k16.row.col.f32.f16.f16.f32 "
        "{%0,%1,%2,%3}, {%4,%5,%6,%7}, {%8,%9}, {%0,%1,%2,%3};"
        : "+f"(c0), "+f"(c1), "+f"(c2), "+f"(c3)
        : "r"(a0), "r"(a1), "r"(a2), "r"(a3), "r"(b0), "r"(b1));
}
static __device__ __forceinline__ void cpa16(uint32_t s, const void* g) {
    asm volatile("cp.async.cg.shared.global [%0], [%1], 16;" :: "r"(s), "l"(g));
}
static __device__ __forceinline__ void cpa_commit() {
    asm volatile("cp.async.commit_group;");
}

// ------------------------------ prep kernels --------------------------------
__global__ void prep_half(const float* __restrict__ src,
                          uint16_t* __restrict__ hi, size_t n4)
{
    uint2* h2 = reinterpret_cast<uint2*>(hi);
    for (size_t i = blockIdx.x * blockDim.x + threadIdx.x; i < n4;
         i += (size_t)gridDim.x * blockDim.x) {
        float4 v = reinterpret_cast<const float4*>(src)[i];
        __half2 h01 = __floats2half2_rn(v.x, v.y);
        __half2 h23 = __floats2half2_rn(v.z, v.w);
        uint2 hu;
        hu.x = *reinterpret_cast<uint32_t*>(&h01);
        hu.y = *reinterpret_cast<uint32_t*>(&h23);
        h2[i] = hu;
    }
}
__global__ void prep_scale_half(const float* __restrict__ U,
                                const float* __restrict__ S,
                                const float* __restrict__ eps,
                                uint16_t* __restrict__ hi, size_t n4, int rq)
{
    uint2* h2 = reinterpret_cast<uint2*>(hi);
    for (size_t i = blockIdx.x * blockDim.x + threadIdx.x; i < n4;
         i += (size_t)gridDim.x * blockDim.x) {
        size_t c4 = i % rq;
        float4 v = reinterpret_cast<const float4*>(U)[i];
        float4 sv = reinterpret_cast<const float4*>(S)[c4];
        float4 ev = reinterpret_cast<const float4*>(eps)[c4];
        v.x *= (sv.x + ev.x); v.y *= (sv.y + ev.y);
        v.z *= (sv.z + ev.z); v.w *= (sv.w + ev.w);
        __half2 h01 = __floats2half2_rn(v.x, v.y);
        __half2 h23 = __floats2half2_rn(v.z, v.w);
        uint2 hu;
        hu.x = *reinterpret_cast<uint32_t*>(&h01);
        hu.y = *reinterpret_cast<uint32_t*>(&h23);
        h2[i] = hu;
    }
}
// Vt [r][dIn] -> vh fp16 [dIn][r] (transpose)
__global__ void prep_transpose_half(const float* __restrict__ Vt,
                                    uint16_t* __restrict__ hi, int R, int dIn)
{
    __shared__ float tile[32][33];
    const int tx = threadIdx.x, ty = threadIdx.y;  // 32 x 8
    const int k0 = blockIdx.y * 32, n0 = blockIdx.x * 32;
    #pragma unroll
    for (int j = 0; j < 4; j++)
        tile[ty + j * 8][tx] = Vt[(size_t)(k0 + ty + j * 8) * dIn + n0 + tx];
    __syncthreads();
    #pragma unroll
    for (int j = 0; j < 4; j++) {
        float v = tile[tx][ty + j * 8];
        __half h = __float2half_rn(v);
        hi[(size_t)(n0 + ty + j * 8) * R + k0 + tx] = *reinterpret_cast<uint16_t*>(&h);
    }
}

// ------------------------------ GEMM core -----------------------------------
// CTA tile 128(m) x 128(n), KC=64 (128B rows, SW128). 8 warps (2m x 4n), 64x32.
// stage: A 16K | B 16K = 32KB; 3 stages = 96KB. 2 CTAs/SM.
#define KC 64
#define T_B 16384
#define STAGE 32768
#define NSTAGE 3
#define SMEM_BYTES (NSTAGE * STAGE)

template<int EPI>   // 0: fp16 output (GEMM1), 1: fp32 + bias (GEMM2)
__global__ __launch_bounds__(256, 2)
void gemm_f16(const uint16_t* __restrict__ Agh,
              const uint16_t* __restrict__ Bgh,
              float* __restrict__ Yout, const float* __restrict__ bias,
              uint16_t* __restrict__ Wh,
              int M, int N, int K)
{
    extern __shared__ char smem[];
    const uint32_t sb = smem_u32(smem);

    const int tid = threadIdx.x;
    const int wid = tid >> 5, lane = tid & 31;
    const int m0 = blockIdx.y * 128;
    const int n0 = blockIdx.x * 128;
    const int mw = (wid & 1) * 64;
    const int nw = (wid >> 1) * 32;

    const uint32_t rowA = mw + (lane & 7) + ((lane >> 3) & 1) * 8;
    const uint32_t colA = ((lane >> 4) & 1) * 16;
    const uint32_t rowB = nw + (lane & 7) + ((lane >> 4) & 1) * 8;
    const uint32_t colB = ((lane >> 3) & 1) * 16;

    float acc[4][4][4];
    #pragma unroll
    for (int i = 0; i < 4; i++)
        #pragma unroll
        for (int j = 0; j < 4; j++)
            #pragma unroll
            for (int q = 0; q < 4; q++) acc[i][j][q] = 0.f;

    const int KI = K / KC;

    // stage loader: 8 cp.async x 16B per thread (A 4, B 4)
    auto ISSUE = [&](int slot, int kt) {
        const uint32_t base = sb + (uint32_t)slot * STAGE;
        const int k0 = kt * KC;
        #pragma unroll
        for (int i = 0; i < 4; i++) {                  // A: 1024 chunks
            int c = tid + i * 256, row = c >> 3, q = c & 7;
            uint32_t off = sw128((uint32_t)(row * 128 + q * 16));
            cpa16(base + off, Agh + (size_t)(m0 + row) * K + k0 + q * 8);
        }
        #pragma unroll
        for (int i = 0; i < 4; i++) {                  // B: 1024 chunks
            int c = tid + i * 256, row = c >> 3, q = c & 7;
            uint32_t off = sw128((uint32_t)(row * 128 + q * 16));
            cpa16(base + T_B + off, Bgh + (size_t)(n0 + row) * K + k0 + q * 8);
        }
        cpa_commit();
    };

    // prologue: fill NSTAGE-1 slots
    ISSUE(0, 0);
    ISSUE(1, 1);

    for (int kt = 0; kt < KI; kt++) {
        asm volatile("cp.async.wait_group %0;" :: "n"(NSTAGE - 2) : "memory");
        __syncthreads();
        if (kt + NSTAGE - 1 < KI)
            ISSUE((kt + NSTAGE - 1) % NSTAGE, kt + NSTAGE - 1);

        const uint32_t Ah = sb + (uint32_t)(kt % NSTAGE) * STAGE;
        const uint32_t Bh = Ah + T_B;

        #pragma unroll
        for (int kk = 0; kk < 4; kk++) {
            uint32_t ah[4][4], bh[2][4];
            #pragma unroll
            for (int mi = 0; mi < 4; mi++) {
                uint32_t off = sw128((rowA + mi * 16) * 128 + kk * 32 + colA);
                ldsm4(ah[mi][0], ah[mi][1], ah[mi][2], ah[mi][3], Ah + off);
            }
            #pragma unroll
            for (int p = 0; p < 2; p++) {
                uint32_t off = sw128((rowB + p * 16) * 128 + kk * 32 + colB);
                ldsm4(bh[p][0], bh[p][1], bh[p][2], bh[p][3], Bh + off);
            }
            #pragma unroll
            for (int mi = 0; mi < 4; mi++) {
                #pragma unroll
                for (int ni = 0; ni < 4; ni++) {
                    float* c = acc[mi][ni];
                    mma16816(c[0], c[1], c[2], c[3],
                             ah[mi][0], ah[mi][1], ah[mi][2], ah[mi][3],
                             bh[ni >> 1][(ni & 1) * 2], bh[ni >> 1][(ni & 1) * 2 + 1]);
                }
            }
        }
    }

    // ------------------------------ epilogue ---------------------------------
    const int erow = lane >> 2;
    const int ecol = (lane & 3) * 2;
    if (EPI == 1) {
        #pragma unroll
        for (int ni = 0; ni < 4; ni++) {
            int n = n0 + nw + ni * 8 + ecol;
            float2 bv = *reinterpret_cast<const float2*>(bias + n);
            #pragma unroll
            for (int mi = 0; mi < 4; mi++) {
                int m = m0 + mw + mi * 16 + erow;
                float* c = acc[mi][ni];
                *reinterpret_cast<float2*>(Yout + (size_t)m * N + n) =
                    make_float2(c[0] + bv.x, c[1] + bv.y);
                *reinterpret_cast<float2*>(Yout + (size_t)(m + 8) * N + n) =
                    make_float2(c[2] + bv.x, c[3] + bv.y);
            }
        }
    } else {
        #pragma unroll
        for (int ni = 0; ni < 4; ni++) {
            int n = n0 + nw + ni * 8 + ecol;
            #pragma unroll
            for (int mi = 0; mi < 4; mi++) {
                int m = m0 + mw + mi * 16 + erow;
                float* c = acc[mi][ni];
                #pragma unroll
                for (int half = 0; half < 2; half++) {
                    __half2 h = __floats2half2_rn(c[half * 2], c[half * 2 + 1]);
                    *reinterpret_cast<uint32_t*>(Wh + (size_t)(m + half * 8) * N + n) =
                        *reinterpret_cast<uint32_t*>(&h);
                }
            }
        }
    }
}

// =============================================================================
// Entry. Inputs: x, U, S, Vt, epsilon, bias
// =============================================================================
extern "C" void kernel_launch(void* const* d_in, const int* in_sizes, int n_in,
                              void* d_out, int out_size)
{
    const float* x    = (const float*)d_in[0];
    const float* U    = (const float*)d_in[1];
    const float* S    = (const float*)d_in[2];
    const float* Vt   = (const float*)d_in[3];
    const float* eps  = (const float*)d_in[4];
    const float* bias = (const float*)d_in[5];
    float* y = (float*)d_out;

    const int r    = in_sizes[2];          // 4096
    const int dIn  = in_sizes[3] / r;      // 4096
    const int dOut = in_sizes[1] / r;      // 4096
    const int M    = in_sizes[0] / dIn;    // 8192

    cudaFuncSetAttribute(gemm_f16<0>, cudaFuncAttributeMaxDynamicSharedMemorySize, SMEM_BYTES);
    cudaFuncSetAttribute(gemm_f16<1>, cudaFuncAttributeMaxDynamicSharedMemorySize, SMEM_BYTES);

    uint16_t *xh, *uh, *vh, *wh;
    cudaGetSymbolAddress((void**)&xh, g_xh);
    cudaGetSymbolAddress((void**)&uh, g_uh);
    cudaGetSymbolAddress((void**)&vh, g_vh);
    cudaGetSymbolAddress((void**)&wh, g_wh);

    prep_half<<<4096, 256>>>(x, xh, (size_t)M * dIn / 4);
    prep_scale_half<<<4096, 256>>>(U, S, eps, uh, (size_t)dOut * r / 4, r / 4);
    {
        dim3 grid(dIn / 32, r / 32), blk(32, 8);
        prep_transpose_half<<<grid, blk>>>(Vt, vh, r, dIn);
    }
    // GEMM1: w[dOut, dIn] = uh @ vh^T (fp16 output)
    {
        dim3 grid(dIn / 128, dOut / 128);
        gemm_f16<0><<<grid, 256, SMEM_BYTES>>>(uh, vh, nullptr, nullptr, wh,
                                               dOut, dIn, r);
    }
    // GEMM2: y[M, dOut] = xh @ wh^T + bias
    {
        dim3 grid(dOut / 128, M / 128);
        gemm_f16<1><<<grid, 256, SMEM_BYTES>>>(xh, wh, y, bias, nullptr,
                                               M, dOut, dIn);
    }
}